// round 12
// baseline (speedup 1.0000x reference)
#include <cuda_runtime.h>
#include <math.h>

#define N_NODES 4096
#define C 256
#define NH 4
#define CH 64
#define ALPHA 0.2f
#define NSPLIT 4
#define NCPART (N_NODES / 32 / NSPLIT)   // 32 chunks of 32 j per split
#define NWORDS (N_NODES / 32)            // 128 bitmask words per row

typedef unsigned long long ull;

// ---------------- device scratch (no allocs allowed) ----------------
__device__ float  g_feats[N_NODES * C];             // 4 MB
__device__ float  g_src[N_NODES * NH];
__device__ float4 g_DE[N_NODES * NH];               // (dst, e^dst, e^(a*dst), -)
__device__ unsigned int g_maxdst_enc[NH];
__device__ unsigned int g_adjbits[N_NODES * NWORDS];// 2 MB bitpacked adjacency
__device__ float  g_pacc[NSPLIT][N_NODES * C];      // 16 MB unnormalized partials
__device__ float  g_pden[NSPLIT][N_NODES * NH];     // partial denominators

__device__ __forceinline__ unsigned int fenc(float f) {
    unsigned int u = __float_as_uint(f);
    return (u & 0x80000000u) ? ~u : (u | 0x80000000u);
}
__device__ __forceinline__ float fdec(unsigned int u) {
    return (u & 0x80000000u) ? __uint_as_float(u ^ 0x80000000u)
                             : __uint_as_float(~u);
}

__device__ __forceinline__ unsigned int sm32(const void* p) {
    unsigned int a;
    asm("{ .reg .u64 t; cvta.to.shared.u64 t, %1; cvt.u32.u64 %0, t; }"
        : "=r"(a) : "l"(p));
    return a;
}

#define CP_ASYNC16(sa, ga) \
    asm volatile("cp.async.cg.shared.global [%0], [%1], 16;" :: "r"(sa), "l"(ga))
#define CP_COMMIT()  asm volatile("cp.async.commit_group;")
#define CP_WAIT0()   asm volatile("cp.async.wait_group 0;" ::: "memory")

// ---------------- init ----------------
__global__ void init_kernel() {
    if (threadIdx.x < NH) g_maxdst_enc[threadIdx.x] = 0u;
}

// ---------------- phase 0: bitpack adjacency ----------------
// one block per row i; warp w handles words w, w+8, ..., ballot per word.
__global__ __launch_bounds__(256) void bitpack_kernel(const int* __restrict__ adj)
{
    const int i    = blockIdx.x;
    const int wp   = threadIdx.x >> 5;
    const int lane = threadIdx.x & 31;
    const int* row = adj + (size_t)i * N_NODES;
#pragma unroll
    for (int t = 0; t < NWORDS / 8; t++) {
        int jw = wp + t * 8;
        int v  = row[jw * 32 + lane];
        unsigned int m = __ballot_sync(0xFFFFFFFFu, v == 1);
        if (lane == 0) g_adjbits[i * NWORDS + jw] = m;
    }
}

// ---------------- phase 1: feats = X @ W + b ----------------
__global__ __launch_bounds__(256) void gemm_feats(
    const float* __restrict__ X, const float* __restrict__ W,
    const float* __restrict__ bias)
{
    __shared__ float As[16][64];
    __shared__ float Bs[16][64];

    const int tid = threadIdx.x;
    const int tx = tid & 15;
    const int ty = tid >> 4;
    const int bm = blockIdx.y * 64;
    const int bn = blockIdx.x * 64;

    float acc[4][4] = {};

    for (int k0 = 0; k0 < C; k0 += 16) {
        {
            int row = tid >> 2;
            int kc  = (tid & 3) * 4;
            float4 v = *(const float4*)&X[(size_t)(bm + row) * C + k0 + kc];
            As[kc + 0][row] = v.x;
            As[kc + 1][row] = v.y;
            As[kc + 2][row] = v.z;
            As[kc + 3][row] = v.w;
        }
        {
            int kr = tid >> 4;
            int cc = (tid & 15) * 4;
            *(float4*)&Bs[kr][cc] =
                *(const float4*)&W[(size_t)(k0 + kr) * C + bn + cc];
        }
        __syncthreads();

#pragma unroll
        for (int kk = 0; kk < 16; kk++) {
            float4 a4 = *(const float4*)&As[kk][ty * 4];
            float4 b4 = *(const float4*)&Bs[kk][tx * 4];
            float av[4] = {a4.x, a4.y, a4.z, a4.w};
            float bv[4] = {b4.x, b4.y, b4.z, b4.w};
#pragma unroll
            for (int i = 0; i < 4; i++)
#pragma unroll
                for (int j = 0; j < 4; j++)
                    acc[i][j] += av[i] * bv[j];
        }
        __syncthreads();
    }

#pragma unroll
    for (int i = 0; i < 4; i++)
#pragma unroll
        for (int j = 0; j < 4; j++) {
            int r = bm + ty * 4 + i;
            int c = bn + tx * 4 + j;
            g_feats[(size_t)r * C + c] = acc[i][j] + bias[c];
        }
}

// ---------------- phase 2: src/dst + exp factors + maxdst ----------------
__global__ __launch_bounds__(256) void srcdst_kernel(const float* __restrict__ a)
{
    const int warp = threadIdx.x >> 5;
    const int lane = threadIdx.x & 31;
    const int n = blockIdx.x * 8 + warp;
    if (n >= N_NODES) return;

    const float* f = g_feats + (size_t)n * C;

#pragma unroll
    for (int h = 0; h < NH; h++) {
        float f0 = f[h * 64 + lane];
        float f1 = f[h * 64 + 32 + lane];
        float as0 = a[h * 128 + lane];
        float as1 = a[h * 128 + 32 + lane];
        float ad0 = a[h * 128 + 64 + lane];
        float ad1 = a[h * 128 + 96 + lane];
        float vs = f0 * as0 + f1 * as1;
        float vd = f0 * ad0 + f1 * ad1;
#pragma unroll
        for (int o = 16; o; o >>= 1) {
            vs += __shfl_xor_sync(0xFFFFFFFFu, vs, o);
            vd += __shfl_xor_sync(0xFFFFFFFFu, vd, o);
        }
        if (lane == 0) {
            g_src[n * NH + h] = vs;
            g_DE[n * NH + h] = make_float4(vd, expf(vd), expf(ALPHA * vd), 0.f);
            atomicMax(&g_maxdst_enc[h], fenc(vd));
        }
    }
}

// ---------------- phase 3: masked-softmax attention + PV (split-j) ----------------
// grid (NH, N/128, NSPLIT); block 256 threads (8 warps), 3 blocks/SM.
// Block tile: 128 i x 64 c; j range per split in 32-chunks.
// Warp wq owns i-strip [wq*16, +16). Adjacency comes from the 2 MB bitmask:
// lane k (k<16) holds the uint32 word for i=ib+k covering this chunk's 32 j;
// lanes get their bit via __shfl (no per-i LDG, no 16-reg prefetch array).
// PV lane map: cg = lane&15 (4 c), ig = lane>>4 (8 i) -> per-j smem traffic:
// feat 2 wf + probs 2 wf (half-broadcast LDS.128; 33-float4 row pad).
// Probs warp-private -> __syncwarp only. Feats via cp.async double-buffer;
// one __syncthreads per chunk. Writes UNNORMALIZED partials + denominators.
__global__ __launch_bounds__(256, 3) void attn_kernel()
{
    __shared__ float  s_feat[2][32][64];    // 16 KB
    __shared__ float4 s_probQ[32][33];      // 16.5 KB  [i-quad][j], padded row
    __shared__ float4 s_SPP[128];           //  2 KB (src, P1, P2, -)

    const int h   = blockIdx.x;
    const int i0  = blockIdx.y * 128;
    const int sp  = blockIdx.z;
    const int jb  = sp * (N_NODES / NSPLIT);   // j base of this split
    const int jw0 = jb / 32;                   // word base of this split
    const int tid = threadIdx.x;
    const int jj  = tid & 31;
    const int wq  = tid >> 5;
    const int ib  = wq * 16;                   // warp i-strip base
    const int cg  = jj & 15;                   // c-quad (4 c)
    const int ig  = jj >> 4;                   // i-group (8 i)

    if (tid < 128) {
        float src = g_src[(i0 + tid) * NH + h];
        float md  = fdec(g_maxdst_enc[h]);
        float bb  = src + md;
        bb = (bb >= 0.f) ? bb : ALPHA * bb;   // b_i >= all logits (all splits!)
        s_SPP[tid] = make_float4(src, expf(src - bb), expf(ALPHA * src - bb), 0.f);
    }
    __syncthreads();

    ull acc[4][4];                            // [i-pair][c] : 8 i x 4 c
#pragma unroll
    for (int p = 0; p < 4; p++)
#pragma unroll
        for (int q = 0; q < 4; q++) acc[p][q] = 0ull;
    float psum[16];
#pragma unroll
    for (int k = 0; k < 16; k++) psum[k] = 0.f;

    const float* fbase = g_feats + (size_t)jb * C + h * 64;
    // bitmask row for this thread's shfl role (lanes 16-31 mirror 0-15)
    const unsigned int* wbase = g_adjbits + (size_t)(i0 + ib + (jj & 15)) * NWORDS + jw0;

    // feat staging: 2 cp.async.16B per thread cover [32][64]
    const int fr0 = tid >> 4;               // 0..15
    const int fc0 = (tid & 15) * 4;
    const int fr1 = fr0 + 16;               // 16..31
    const unsigned int sA0 = sm32(&s_feat[0][fr0][fc0]);
    const unsigned int sA1 = sm32(&s_feat[0][fr1][fc0]);
    const unsigned int sB0 = sm32(&s_feat[1][fr0][fc0]);
    const unsigned int sB1 = sm32(&s_feat[1][fr1][fc0]);

    // ---- prologue: chunk 0 of this split ----
    CP_ASYNC16(sA0, &fbase[(size_t)fr0 * C + fc0]);
    CP_ASYNC16(sA1, &fbase[(size_t)fr1 * C + fc0]);
    CP_COMMIT();
    unsigned int word = wbase[0];
    float4 de = g_DE[(jb + jj) * NH + h];

    const int rowA = wq * 4 + 2 * ig;        // this thread's 2 prob rows
    const int rowB = rowA + 1;

    for (int c = 0; c < NCPART; c++) {
        const int buf = c & 1;

        // ---- probs for chunk c (warp-private region of s_probQ) ----
        __syncwarp();
        {
            float pr[16];
#pragma unroll
            for (int k = 0; k < 16; k++) {
                unsigned int wk = __shfl_sync(0xFFFFFFFFu, word, k);
                float4 spp = s_SPP[ib + k];
                float s = spp.x + de.x;
                float p = ((wk >> jj) & 1u)
                            ? ((s >= 0.f) ? spp.y * de.y : spp.z * de.z)
                            : 0.f;
                pr[k] = p;
                psum[k] += p;
            }
#pragma unroll
            for (int q = 0; q < 4; q++)
                s_probQ[wq * 4 + q][jj] =
                    make_float4(pr[4 * q], pr[4 * q + 1], pr[4 * q + 2], pr[4 * q + 3]);
        }

        CP_WAIT0();
        __syncthreads();

        // ---- prefetch chunk c+1 (overlaps PV below) ----
        if (c + 1 < NCPART) {
            const int j0n = (c + 1) * 32;
            if (buf == 0) {
                CP_ASYNC16(sB0, &fbase[(size_t)(j0n + fr0) * C + fc0]);
                CP_ASYNC16(sB1, &fbase[(size_t)(j0n + fr1) * C + fc0]);
            } else {
                CP_ASYNC16(sA0, &fbase[(size_t)(j0n + fr0) * C + fc0]);
                CP_ASYNC16(sA1, &fbase[(size_t)(j0n + fr1) * C + fc0]);
            }
            CP_COMMIT();
            word = wbase[c + 1];
            de = g_DE[(size_t)(jb + j0n + jj) * NH + h];
        }

        // ---- PV chunk c: 8 i x 4 c per thread, packed fp32 FMA ----
#pragma unroll 8
        for (int j = 0; j < 32; j++) {
            float4 fq = *(const float4*)&s_feat[buf][j][cg * 4];
            ull f0, f1, f2, f3;
            asm("mov.b64 %0, {%1, %1};" : "=l"(f0) : "f"(fq.x));
            asm("mov.b64 %0, {%1, %1};" : "=l"(f1) : "f"(fq.y));
            asm("mov.b64 %0, {%1, %1};" : "=l"(f2) : "f"(fq.z));
            asm("mov.b64 %0, {%1, %1};" : "=l"(f3) : "f"(fq.w));
            ulonglong2 pA = *(const ulonglong2*)&s_probQ[rowA][j];  // i-pairs 0,1
            ulonglong2 pB = *(const ulonglong2*)&s_probQ[rowB][j];  // i-pairs 2,3
            asm("fma.rn.f32x2 %0, %1, %2, %0;" : "+l"(acc[0][0]) : "l"(pA.x), "l"(f0));
            asm("fma.rn.f32x2 %0, %1, %2, %0;" : "+l"(acc[0][1]) : "l"(pA.x), "l"(f1));
            asm("fma.rn.f32x2 %0, %1, %2, %0;" : "+l"(acc[0][2]) : "l"(pA.x), "l"(f2));
            asm("fma.rn.f32x2 %0, %1, %2, %0;" : "+l"(acc[0][3]) : "l"(pA.x), "l"(f3));
            asm("fma.rn.f32x2 %0, %1, %2, %0;" : "+l"(acc[1][0]) : "l"(pA.y), "l"(f0));
            asm("fma.rn.f32x2 %0, %1, %2, %0;" : "+l"(acc[1][1]) : "l"(pA.y), "l"(f1));
            asm("fma.rn.f32x2 %0, %1, %2, %0;" : "+l"(acc[1][2]) : "l"(pA.y), "l"(f2));
            asm("fma.rn.f32x2 %0, %1, %2, %0;" : "+l"(acc[1][3]) : "l"(pA.y), "l"(f3));
            asm("fma.rn.f32x2 %0, %1, %2, %0;" : "+l"(acc[2][0]) : "l"(pB.x), "l"(f0));
            asm("fma.rn.f32x2 %0, %1, %2, %0;" : "+l"(acc[2][1]) : "l"(pB.x), "l"(f1));
            asm("fma.rn.f32x2 %0, %1, %2, %0;" : "+l"(acc[2][2]) : "l"(pB.x), "l"(f2));
            asm("fma.rn.f32x2 %0, %1, %2, %0;" : "+l"(acc[2][3]) : "l"(pB.x), "l"(f3));
            asm("fma.rn.f32x2 %0, %1, %2, %0;" : "+l"(acc[3][0]) : "l"(pB.y), "l"(f0));
            asm("fma.rn.f32x2 %0, %1, %2, %0;" : "+l"(acc[3][1]) : "l"(pB.y), "l"(f1));
            asm("fma.rn.f32x2 %0, %1, %2, %0;" : "+l"(acc[3][2]) : "l"(pB.y), "l"(f2));
            asm("fma.rn.f32x2 %0, %1, %2, %0;" : "+l"(acc[3][3]) : "l"(pB.y), "l"(f3));
        }
    }

    // ---- partial denominators ----
#pragma unroll
    for (int k = 0; k < 16; k++) {
        float v = psum[k];
#pragma unroll
        for (int o = 16; o; o >>= 1) v += __shfl_xor_sync(0xFFFFFFFFu, v, o);
        if (jj == 0) g_pden[sp][(i0 + ib + k) * NH + h] = v;
    }

    // ---- write unnormalized partial accumulators (float4, coalesced) ----
    float* pacc = g_pacc[sp];
#pragma unroll
    for (int p = 0; p < 4; p++) {
        int iloc = ib + ig * 8 + 2 * p;
        float lo[4], hi[4];
#pragma unroll
        for (int q = 0; q < 4; q++)
            asm("mov.b64 {%0, %1}, %2;" : "=f"(lo[q]), "=f"(hi[q]) : "l"(acc[p][q]));
        *(float4*)&pacc[(size_t)(i0 + iloc) * C + h * 64 + cg * 4] =
            make_float4(lo[0], lo[1], lo[2], lo[3]);
        *(float4*)&pacc[(size_t)(i0 + iloc + 1) * C + h * 64 + cg * 4] =
            make_float4(hi[0], hi[1], hi[2], hi[3]);
    }
}

// ---------------- phase 4: combine splits + normalize ----------------
__global__ __launch_bounds__(256) void combine_kernel(float* __restrict__ out)
{
    int idx = blockIdx.x * 256 + threadIdx.x;       // over N*C/4 float4 groups
    int i = idx >> 6;
    int h = (idx >> 4) & 3;
    float4 a = *(const float4*)&g_pacc[0][(size_t)idx * 4];
    float4 b = *(const float4*)&g_pacc[1][(size_t)idx * 4];
    float4 cc = *(const float4*)&g_pacc[2][(size_t)idx * 4];
    float4 d = *(const float4*)&g_pacc[3][(size_t)idx * 4];
    float den = (g_pden[0][i * NH + h] + g_pden[1][i * NH + h]) +
                (g_pden[2][i * NH + h] + g_pden[3][i * NH + h]);
    float r = 1.f / den;
    float4 v = make_float4(((a.x + b.x) + (cc.x + d.x)) * r,
                           ((a.y + b.y) + (cc.y + d.y)) * r,
                           ((a.z + b.z) + (cc.z + d.z)) * r,
                           ((a.w + b.w) + (cc.w + d.w)) * r);
    *(float4*)&out[(size_t)idx * 4] = v;
}

// ---------------- launch ----------------
extern "C" void kernel_launch(void* const* d_in, const int* in_sizes, int n_in,
                              void* d_out, int out_size)
{
    const float* node_feats = (const float*)d_in[0];
    const int*   adj        = (const int*)d_in[1];
    const float* W          = (const float*)d_in[2];
    const float* b          = (const float*)d_in[3];
    const float* a          = (const float*)d_in[4];
    float* out = (float*)d_out;

    init_kernel<<<1, 32>>>();
    bitpack_kernel<<<N_NODES, 256>>>(adj);
    gemm_feats<<<dim3(C / 64, N_NODES / 64), 256>>>(node_feats, W, b);
    srcdst_kernel<<<N_NODES / 8, 256>>>(a);
    attn_kernel<<<dim3(NH, N_NODES / 128, NSPLIT), 256>>>();
    combine_kernel<<<(N_NODES * C / 4) / 256, 256>>>(out);
}

// round 15
// speedup vs baseline: 1.0729x; 1.0729x over previous
#include <cuda_runtime.h>
#include <cuda_bf16.h>
#include <math.h>
#include <stdint.h>

#define N_NODES 4096
#define C 256
#define NH 4
#define ALPHA 0.2f
#define NWORDS (N_NODES / 32)   // 128 bitmask words per row
#define JC 32                   // j per chunk
#define NCH (N_NODES / JC)      // 128 chunks

typedef unsigned long long ull;

// ---------------- device scratch (no allocs allowed) ----------------
__device__ float  g_feats[N_NODES * C];              // 4 MB
__device__ float  g_src[N_NODES * NH];
__device__ float4 g_DE[N_NODES * NH];                // (dst, e^dst, e^(a*dst), -)
__device__ unsigned int g_maxdst_enc[NH];
__device__ unsigned int g_adjbits[N_NODES * NWORDS]; // 2 MB bitpacked adjacency
__device__ unsigned int g_fhi[N_NODES * C / 2];      // feats hi bf16x2 [j][hc]
__device__ unsigned int g_flo[N_NODES * C / 2];      // feats lo bf16x2

__device__ __forceinline__ unsigned int fenc(float f) {
    unsigned int u = __float_as_uint(f);
    return (u & 0x80000000u) ? ~u : (u | 0x80000000u);
}
__device__ __forceinline__ float fdec(unsigned int u) {
    return (u & 0x80000000u) ? __uint_as_float(u ^ 0x80000000u)
                             : __uint_as_float(~u);
}
__device__ __forceinline__ unsigned int sm32(const void* p) {
    unsigned int a;
    asm("{ .reg .u64 t; cvta.to.shared.u64 t, %1; cvt.u32.u64 %0, t; }"
        : "=r"(a) : "l"(p));
    return a;
}

#define CP_ASYNC16(sa, ga) \
    asm volatile("cp.async.cg.shared.global [%0], [%1], 16;" :: "r"(sa), "l"(ga))
#define CP_COMMIT()  asm volatile("cp.async.commit_group;")
#define CP_WAIT1()   asm volatile("cp.async.wait_group 1;" ::: "memory")
#define CP_WAIT0()   asm volatile("cp.async.wait_group 0;" ::: "memory")

// pack two fp32 -> bf16x2 (low half = lo arg)
#define PACK2(r, lo, hi) \
    asm("cvt.rn.bf16x2.f32 %0, %1, %2;" : "=r"(r) : "f"(hi), "f"(lo))

#define LDSM4(r0, r1, r2, r3, addr) \
    asm volatile("ldmatrix.sync.aligned.m8n8.x4.shared.b16 {%0,%1,%2,%3}, [%4];" \
        : "=r"(r0), "=r"(r1), "=r"(r2), "=r"(r3) : "r"(addr))
#define LDSM4T(r0, r1, r2, r3, addr) \
    asm volatile("ldmatrix.sync.aligned.m8n8.x4.trans.shared.b16 {%0,%1,%2,%3}, [%4];" \
        : "=r"(r0), "=r"(r1), "=r"(r2), "=r"(r3) : "r"(addr))

#define MMA(d, a0, a1, a2, a3, b0, b1) \
    asm volatile("mma.sync.aligned.m16n8k16.row.col.f32.bf16.bf16.f32 " \
        "{%0,%1,%2,%3},{%4,%5,%6,%7},{%8,%9},{%0,%1,%2,%3};" \
        : "+f"((d)[0]), "+f"((d)[1]), "+f"((d)[2]), "+f"((d)[3]) \
        : "r"(a0), "r"(a1), "r"(a2), "r"(a3), "r"(b0), "r"(b1))

// ---------------- init ----------------
__global__ void init_kernel() {
    if (threadIdx.x < NH) g_maxdst_enc[threadIdx.x] = 0u;
}

// ---------------- phase 0: bitpack adjacency ----------------
__global__ __launch_bounds__(256) void bitpack_kernel(const int* __restrict__ adj)
{
    const int i    = blockIdx.x;
    const int wp   = threadIdx.x >> 5;
    const int lane = threadIdx.x & 31;
    const int* row = adj + (size_t)i * N_NODES;
#pragma unroll
    for (int t = 0; t < NWORDS / 8; t++) {
        int jw = wp + t * 8;
        int v  = row[jw * 32 + lane];
        unsigned int m = __ballot_sync(0xFFFFFFFFu, v == 1);
        if (lane == 0) g_adjbits[i * NWORDS + jw] = m;
    }
}

// ---------------- phase 1: feats = X @ W + b ----------------
__global__ __launch_bounds__(256) void gemm_feats(
    const float* __restrict__ X, const float* __restrict__ W,
    const float* __restrict__ bias)
{
    __shared__ float As[16][64];
    __shared__ float Bs[16][64];

    const int tid = threadIdx.x;
    const int tx = tid & 15;
    const int ty = tid >> 4;
    const int bm = blockIdx.y * 64;
    const int bn = blockIdx.x * 64;

    float acc[4][4] = {};

    for (int k0 = 0; k0 < C; k0 += 16) {
        {
            int row = tid >> 2;
            int kc  = (tid & 3) * 4;
            float4 v = *(const float4*)&X[(size_t)(bm + row) * C + k0 + kc];
            As[kc + 0][row] = v.x;
            As[kc + 1][row] = v.y;
            As[kc + 2][row] = v.z;
            As[kc + 3][row] = v.w;
        }
        {
            int kr = tid >> 4;
            int cc = (tid & 15) * 4;
            *(float4*)&Bs[kr][cc] =
                *(const float4*)&W[(size_t)(k0 + kr) * C + bn + cc];
        }
        __syncthreads();

#pragma unroll
        for (int kk = 0; kk < 16; kk++) {
            float4 a4 = *(const float4*)&As[kk][ty * 4];
            float4 b4 = *(const float4*)&Bs[kk][tx * 4];
            float av[4] = {a4.x, a4.y, a4.z, a4.w};
            float bv[4] = {b4.x, b4.y, b4.z, b4.w};
#pragma unroll
            for (int i = 0; i < 4; i++)
#pragma unroll
                for (int j = 0; j < 4; j++)
                    acc[i][j] += av[i] * bv[j];
        }
        __syncthreads();
    }

#pragma unroll
    for (int i = 0; i < 4; i++)
#pragma unroll
        for (int j = 0; j < 4; j++) {
            int r = bm + ty * 4 + i;
            int c = bn + tx * 4 + j;
            g_feats[(size_t)r * C + c] = acc[i][j] + bias[c];
        }
}

// ---------------- phase 2: src/dst + exp factors + maxdst ----------------
__global__ __launch_bounds__(256) void srcdst_kernel(const float* __restrict__ a)
{
    const int warp = threadIdx.x >> 5;
    const int lane = threadIdx.x & 31;
    const int n = blockIdx.x * 8 + warp;
    if (n >= N_NODES) return;

    const float* f = g_feats + (size_t)n * C;

#pragma unroll
    for (int h = 0; h < NH; h++) {
        float f0 = f[h * 64 + lane];
        float f1 = f[h * 64 + 32 + lane];
        float as0 = a[h * 128 + lane];
        float as1 = a[h * 128 + 32 + lane];
        float ad0 = a[h * 128 + 64 + lane];
        float ad1 = a[h * 128 + 96 + lane];
        float vs = f0 * as0 + f1 * as1;
        float vd = f0 * ad0 + f1 * ad1;
#pragma unroll
        for (int o = 16; o; o >>= 1) {
            vs += __shfl_xor_sync(0xFFFFFFFFu, vs, o);
            vd += __shfl_xor_sync(0xFFFFFFFFu, vd, o);
        }
        if (lane == 0) {
            g_src[n * NH + h] = vs;
            g_DE[n * NH + h] = make_float4(vd, expf(vd), expf(ALPHA * vd), 0.f);
            atomicMax(&g_maxdst_enc[h], fenc(vd));
        }
    }
}

// ---------------- phase 2b: split feats into bf16 hi/lo ([j][hc] layout) ----
__global__ __launch_bounds__(256) void feat_split_kernel()
{
    int idx = blockIdx.x * 256 + threadIdx.x;   // over N*C/4 float4 groups
    float4 v = *(const float4*)&g_feats[(size_t)idx * 4];
    unsigned int h0, h1;
    PACK2(h0, v.x, v.y);
    PACK2(h1, v.z, v.w);
    float e0 = __uint_as_float(h0 << 16);
    float e1 = __uint_as_float(h0 & 0xFFFF0000u);
    float e2 = __uint_as_float(h1 << 16);
    float e3 = __uint_as_float(h1 & 0xFFFF0000u);
    unsigned int l0, l1;
    PACK2(l0, v.x - e0, v.y - e1);
    PACK2(l1, v.z - e2, v.w - e3);
    *(uint2*)&g_fhi[(size_t)idx * 2] = make_uint2(h0, h1);
    *(uint2*)&g_flo[(size_t)idx * 2] = make_uint2(l0, l1);
}

// ---------------- phase 3: attention via mma.sync bf16 (3-term split) -------
// grid (NH, N/128) = 128 blocks, 256 threads (8 warps), 1 block/SM.
// Warp wq owns rows [wq*16, +16) x all 64 c; accum = 32 fp32 regs/lane.
// Per 32-j chunk: thread (il=tid&127, half=tid>>7) computes 16 probs for row
// il (factored-softmax, adjacency bit from g_adjbits), splits to bf16 hi/lo,
// STS.128 into P tiles [128][40bf16] (pad 40 -> conflict-free ldmatrix rows
// AND 4-phase-optimal STS). F^T tiles [32j][72bf16] (pad 72 -> conflict-free
// ldmatrix.trans) staged by cp.async, TRIPLE-buffered. One __syncthreads per
// chunk. 48 HMMA/warp/chunk: PhiFhi + PhiFlo + PloFhi, interleaved across 2
// n-blocks to break accumulator dependency chains.
static const int OFF_PHI  = 0;        // 2 x 10240
static const int OFF_PLO  = 20480;    // 2 x 10240
static const int OFF_FHI  = 40960;    // 3 x 4608
static const int OFF_FLO  = 54784;    // 3 x 4608
static const int OFF_DE   = 68608;    // 2 x 32 float4
static const int OFF_RED  = 69632;    // 256 float
static const int OFF_ISUM = 70656;    // 128 float
static const int ATTN_SMEM = 71680;

__global__ __launch_bounds__(256) void attn_kernel(float* __restrict__ out)
{
    extern __shared__ char sb[];
    const unsigned int sbase = sm32(sb);

    const int h    = blockIdx.x;
    const int i0   = blockIdx.y * 128;
    const int tid  = threadIdx.x;
    const int wq   = tid >> 5;
    const int lane = tid & 31;
    const int il   = tid & 127;
    const int half = tid >> 7;

    // ---- per-thread softmax factors for row il ----
    float srcv = g_src[(i0 + il) * NH + h];
    float md   = fdec(g_maxdst_enc[h]);
    float bb   = srcv + md;
    bb = (bb >= 0.f) ? bb : ALPHA * bb;        // b_i >= all logits
    const float P1 = expf(srcv - bb);
    const float P2 = expf(ALPHA * srcv - bb);
    float den = 0.f;

    // ---- F staging: thread -> (row fj, 16B seg) of the 32x128B chunk ----
    const int fj  = tid >> 3;                  // 0..31
    const int seg = tid & 7;                   // 0..7
    const char* gfh = (const char*)g_fhi + ((size_t)fj * C + h * 64) * 2 + seg * 16;
    const char* gfl = (const char*)g_flo + ((size_t)fj * C + h * 64) * 2 + seg * 16;
    const unsigned int sFh = sbase + OFF_FHI + fj * 144 + seg * 16;
    const unsigned int sFl = sbase + OFF_FLO + fj * 144 + seg * 16;

    // ---- prologue: F(0) -> slot 0, DE(0), adj word(0) ----
    CP_ASYNC16(sFh, gfh);
    CP_ASYNC16(sFl, gfl);
    CP_COMMIT();
    if (tid < 32)
        *(float4*)(sb + OFF_DE + tid * 16) = g_DE[(size_t)tid * NH + h];
    unsigned int word = g_adjbits[(size_t)(i0 + il) * NWORDS];
    __syncthreads();   // DE(0) visible to ALL threads before probs(0)

    float d[8][4];
#pragma unroll
    for (int nb = 0; nb < 8; nb++)
#pragma unroll
        for (int q = 0; q < 4; q++) d[nb][q] = 0.f;

    for (int c = 0; c < NCH; c++) {
        const int buf   = c & 1;
        const int fslot = c % 3;

        // ---- probs: 16 j for row il, bf16 split, 4x STS.128 ----
        {
            const float4* deb = (const float4*)(sb + OFF_DE + buf * 512);
            float pr[16];
#pragma unroll
            for (int u = 0; u < 16; u++) {
                int jl = half * 16 + u;
                float4 d4 = deb[jl];
                float s = srcv + d4.x;
                float v = (s >= 0.f) ? P1 * d4.y : P2 * d4.z;
                pr[u] = ((word >> jl) & 1u) ? v : 0.f;
                den += pr[u];
            }
            unsigned int hp[8], lp[8];
#pragma unroll
            for (int q = 0; q < 8; q++) {
                unsigned int hh;
                PACK2(hh, pr[2 * q], pr[2 * q + 1]);
                float e0 = __uint_as_float(hh << 16);
                float e1 = __uint_as_float(hh & 0xFFFF0000u);
                unsigned int ll;
                PACK2(ll, pr[2 * q] - e0, pr[2 * q + 1] - e1);
                hp[q] = hh;
                lp[q] = ll;
            }
            char* pH = sb + OFF_PHI + buf * 10240 + il * 80 + half * 32;
            char* pL = sb + OFF_PLO + buf * 10240 + il * 80 + half * 32;
            *(uint4*)pH        = make_uint4(hp[0], hp[1], hp[2], hp[3]);
            *(uint4*)(pH + 16) = make_uint4(hp[4], hp[5], hp[6], hp[7]);
            *(uint4*)pL        = make_uint4(lp[0], lp[1], lp[2], lp[3]);
            *(uint4*)(pL + 16) = make_uint4(lp[4], lp[5], lp[6], lp[7]);
        }

        // ---- prefetch chunk c+1 ----
        if (c + 1 < NCH) {
            const int ns = (c + 1) % 3;
            const size_t go = (size_t)(c + 1) * JC * C * 2;   // 32 rows x 512B
            CP_ASYNC16(sFh + ns * 4608, gfh + go);
            CP_ASYNC16(sFl + ns * 4608, gfl + go);
            CP_COMMIT();
            if (tid < 32)
                *(float4*)(sb + OFF_DE + (buf ^ 1) * 512 + tid * 16) =
                    g_DE[(size_t)((c + 1) * JC + tid) * NH + h];
            word = g_adjbits[(size_t)(i0 + il) * NWORDS + c + 1];
            CP_WAIT1();     // F(c) arrived
        } else {
            CP_WAIT0();
        }
        __syncthreads();    // P(c), F(c), DE(c+1) visible block-wide

        // ---- mma: A = P rows [wq*16,+16) x k32, B = F k32 x n64 ----
        {
            const unsigned int lrow = lane & 15;
            const unsigned int lsel = (lane >> 4) * 16;
            unsigned int pAh = sbase + OFF_PHI + buf * 10240 + wq * 16 * 80
                               + lrow * 80 + lsel;
            unsigned int pAl = pAh + (OFF_PLO - OFF_PHI);
            unsigned int pBh = sbase + OFF_FHI + fslot * 4608 + lrow * 144 + lsel;
            unsigned int pBl = pBh + (OFF_FLO - OFF_FHI);

            unsigned int aH0[4], aH1[4], aL0[4], aL1[4];
            LDSM4(aH0[0], aH0[1], aH0[2], aH0[3], pAh);
            LDSM4(aH1[0], aH1[1], aH1[2], aH1[3], pAh + 32);
            LDSM4(aL0[0], aL0[1], aL0[2], aL0[3], pAl);
            LDSM4(aL1[0], aL1[1], aL1[2], aL1[3], pAl + 32);

#pragma unroll
            for (int nt = 0; nt < 4; nt++) {
                unsigned int bH0[4], bH1[4], bL0[4], bL1[4];
                LDSM4T(bH0[0], bH0[1], bH0[2], bH0[3], pBh + nt * 32);
                LDSM4T(bH1[0], bH1[1], bH1[2], bH1[3], pBh + 2304 + nt * 32);
                LDSM4T(bL0[0], bL0[1], bL0[2], bL0[3], pBl + nt * 32);
                LDSM4T(bL1[0], bL1[1], bL1[2], bL1[3], pBl + 2304 + nt * 32);
                float* dA = d[nt * 2];
                float* dB = d[nt * 2 + 1];
                // interleave the two n-blocks to break accumulator chains
                MMA(dA, aH0[0], aH0[1], aH0[2], aH0[3], bH0[0], bH0[1]);
                MMA(dB, aH0[0], aH0[1], aH0[2], aH0[3], bH0[2], bH0[3]);
                MMA(dA, aH1[0], aH1[1], aH1[2], aH1[3], bH1[0], bH1[1]);
                MMA(dB, aH1[0], aH1[1], aH1[2], aH1[3], bH1[2], bH1[3]);
                MMA(dA, aH0[0], aH0[1], aH0[2], aH0[3], bL0[0], bL0[1]);
                MMA(dB, aH0[0], aH0[1], aH0[2], aH0[3], bL0[2], bL0[3]);
                MMA(dA, aH1[0], aH1[1], aH1[2], aH1[3], bL1[0], bL1[1]);
                MMA(dB, aH1[0], aH1[1], aH1[2], aH1[3], bL1[2], bL1[3]);
                MMA(dA, aL0[0], aL0[1], aL0[2], aL0[3], bH0[0], bH0[1]);
                MMA(dB, aL0[0], aL0[1], aL0[2], aL0[3], bH0[2], bH0[3]);
                MMA(dA, aL1[0], aL1[1], aL1[2], aL1[3], bH1[0], bH1[1]);
                MMA(dB, aL1[0], aL1[1], aL1[2], aL1[3], bH1[2], bH1[3]);
            }
        }
    }

    // ---- denominators ----
    ((float*)(sb + OFF_RED))[half * 128 + il] = den;
    __syncthreads();
    if (tid < 128) {
        float d0 = ((float*)(sb + OFF_RED))[tid];
        float d1 = ((float*)(sb + OFF_RED))[128 + tid];
        ((float*)(sb + OFF_ISUM))[tid] = 1.f / (d0 + d1);
    }
    __syncthreads();

    // ---- normalize + store ----
    {
        const int g = lane >> 2;
        const int t = lane & 3;
        const int ib = wq * 16;
        float r0 = ((float*)(sb + OFF_ISUM))[ib + g];
        float r1 = ((float*)(sb + OFF_ISUM))[ib + g + 8];
#pragma unroll
        for (int nb = 0; nb < 8; nb++) {
            int col = h * 64 + nb * 8 + 2 * t;
            *(float2*)&out[(size_t)(i0 + ib + g) * C + col] =
                make_float2(d[nb][0] * r0, d[nb][1] * r0);
            *(float2*)&out[(size_t)(i0 + ib + g + 8) * C + col] =
                make_float2(d[nb][2] * r1, d[nb][3] * r1);
        }
    }
}

// ---------------- launch ----------------
extern "C" void kernel_launch(void* const* d_in, const int* in_sizes, int n_in,
                              void* d_out, int out_size)
{
    const float* node_feats = (const float*)d_in[0];
    const int*   adj        = (const int*)d_in[1];
    const float* W          = (const float*)d_in[2];
    const float* b          = (const float*)d_in[3];
    const float* a          = (const float*)d_in[4];
    float* out = (float*)d_out;

    cudaFuncSetAttribute(attn_kernel,
                         cudaFuncAttributeMaxDynamicSharedMemorySize, ATTN_SMEM);

    init_kernel<<<1, 32>>>();
    bitpack_kernel<<<N_NODES, 256>>>(adj);
    gemm_feats<<<dim3(C / 64, N_NODES / 64), 256>>>(node_feats, W, b);
    srcdst_kernel<<<N_NODES / 8, 256>>>(a);
    feat_split_kernel<<<(N_NODES * C / 4) / 256, 256>>>();
    attn_kernel<<<dim3(NH, N_NODES / 128), 256, ATTN_SMEM>>>(out);
}

// round 16
// speedup vs baseline: 1.8320x; 1.7075x over previous
#include <cuda_runtime.h>
#include <cuda_bf16.h>
#include <math.h>
#include <stdint.h>

#define N_NODES 4096
#define C 256
#define NH 4
#define ALPHA 0.2f
#define NWORDS (N_NODES / 32)   // 128 bitmask words per row
#define JC 32                   // j per chunk
#define NSPLIT 2
#define NCPART (N_NODES / JC / NSPLIT)   // 64 chunks per split

typedef unsigned long long ull;

// ---------------- device scratch (no allocs allowed) ----------------
__device__ float  g_feats[N_NODES * C];              // 4 MB
__device__ float  g_src[N_NODES * NH];
__device__ float4 g_DE[N_NODES * NH];                // (dst, e^dst, e^(a*dst), -)
__device__ unsigned int g_maxdst_enc[NH];
__device__ unsigned int g_adjbits[N_NODES * NWORDS]; // 2 MB bitpacked adjacency
__device__ unsigned int g_fhi[N_NODES * C / 2];      // feats hi bf16x2 [j][hc]
__device__ unsigned int g_flo[N_NODES * C / 2];      // feats lo bf16x2
__device__ float  g_pacc[NSPLIT][N_NODES * C];       // 8 MB unnormalized partials
__device__ float  g_pden[NSPLIT][N_NODES * NH];      // partial denominators

__device__ __forceinline__ unsigned int fenc(float f) {
    unsigned int u = __float_as_uint(f);
    return (u & 0x80000000u) ? ~u : (u | 0x80000000u);
}
__device__ __forceinline__ float fdec(unsigned int u) {
    return (u & 0x80000000u) ? __uint_as_float(u ^ 0x80000000u)
                             : __uint_as_float(~u);
}
__device__ __forceinline__ unsigned int sm32(const void* p) {
    unsigned int a;
    asm("{ .reg .u64 t; cvta.to.shared.u64 t, %1; cvt.u32.u64 %0, t; }"
        : "=r"(a) : "l"(p));
    return a;
}

#define CP_ASYNC16(sa, ga) \
    asm volatile("cp.async.cg.shared.global [%0], [%1], 16;" :: "r"(sa), "l"(ga))
#define CP_COMMIT()  asm volatile("cp.async.commit_group;")
#define CP_WAIT1()   asm volatile("cp.async.wait_group 1;" ::: "memory")
#define CP_WAIT0()   asm volatile("cp.async.wait_group 0;" ::: "memory")

// pack two fp32 -> bf16x2 (low half = lo arg)
#define PACK2(r, lo, hi) \
    asm("cvt.rn.bf16x2.f32 %0, %1, %2;" : "=r"(r) : "f"(hi), "f"(lo))

#define LDSM4(r0, r1, r2, r3, addr) \
    asm volatile("ldmatrix.sync.aligned.m8n8.x4.shared.b16 {%0,%1,%2,%3}, [%4];" \
        : "=r"(r0), "=r"(r1), "=r"(r2), "=r"(r3) : "r"(addr))
#define LDSM4T(r0, r1, r2, r3, addr) \
    asm volatile("ldmatrix.sync.aligned.m8n8.x4.trans.shared.b16 {%0,%1,%2,%3}, [%4];" \
        : "=r"(r0), "=r"(r1), "=r"(r2), "=r"(r3) : "r"(addr))

#define MMA(d, a0, a1, a2, a3, b0, b1) \
    asm volatile("mma.sync.aligned.m16n8k16.row.col.f32.bf16.bf16.f32 " \
        "{%0,%1,%2,%3},{%4,%5,%6,%7},{%8,%9},{%0,%1,%2,%3};" \
        : "+f"((d)[0]), "+f"((d)[1]), "+f"((d)[2]), "+f"((d)[3]) \
        : "r"(a0), "r"(a1), "r"(a2), "r"(a3), "r"(b0), "r"(b1))

// ---------------- init ----------------
__global__ void init_kernel() {
    if (threadIdx.x < NH) g_maxdst_enc[threadIdx.x] = 0u;
}

// ---------------- phase 0: bitpack adjacency ----------------
__global__ __launch_bounds__(256) void bitpack_kernel(const int* __restrict__ adj)
{
    const int i    = blockIdx.x;
    const int wp   = threadIdx.x >> 5;
    const int lane = threadIdx.x & 31;
    const int* row = adj + (size_t)i * N_NODES;
#pragma unroll
    for (int t = 0; t < NWORDS / 8; t++) {
        int jw = wp + t * 8;
        int v  = row[jw * 32 + lane];
        unsigned int m = __ballot_sync(0xFFFFFFFFu, v == 1);
        if (lane == 0) g_adjbits[i * NWORDS + jw] = m;
    }
}

// ---------------- phase 1: feats = X @ W + b  (+ fused bf16 hi/lo split) ----
__global__ __launch_bounds__(256) void gemm_feats(
    const float* __restrict__ X, const float* __restrict__ W,
    const float* __restrict__ bias)
{
    __shared__ float As[16][64];
    __shared__ float Bs[16][64];

    const int tid = threadIdx.x;
    const int tx = tid & 15;
    const int ty = tid >> 4;
    const int bm = blockIdx.y * 64;
    const int bn = blockIdx.x * 64;

    float acc[4][4] = {};

    for (int k0 = 0; k0 < C; k0 += 16) {
        {
            int row = tid >> 2;
            int kc  = (tid & 3) * 4;
            float4 v = *(const float4*)&X[(size_t)(bm + row) * C + k0 + kc];
            As[kc + 0][row] = v.x;
            As[kc + 1][row] = v.y;
            As[kc + 2][row] = v.z;
            As[kc + 3][row] = v.w;
        }
        {
            int kr = tid >> 4;
            int cc = (tid & 15) * 4;
            *(float4*)&Bs[kr][cc] =
                *(const float4*)&W[(size_t)(k0 + kr) * C + bn + cc];
        }
        __syncthreads();

#pragma unroll
        for (int kk = 0; kk < 16; kk++) {
            float4 a4 = *(const float4*)&As[kk][ty * 4];
            float4 b4 = *(const float4*)&Bs[kk][tx * 4];
            float av[4] = {a4.x, a4.y, a4.z, a4.w};
            float bv[4] = {b4.x, b4.y, b4.z, b4.w};
#pragma unroll
            for (int i = 0; i < 4; i++)
#pragma unroll
                for (int j = 0; j < 4; j++)
                    acc[i][j] += av[i] * bv[j];
        }
        __syncthreads();
    }

    // epilogue: write fp32 feats + bf16 hi/lo splits (fused feat_split)
#pragma unroll
    for (int i = 0; i < 4; i++) {
        int r = bm + ty * 4 + i;
        int c = bn + tx * 4;
        float v0 = acc[i][0] + bias[c];
        float v1 = acc[i][1] + bias[c + 1];
        float v2 = acc[i][2] + bias[c + 2];
        float v3 = acc[i][3] + bias[c + 3];
        *(float4*)&g_feats[(size_t)r * C + c] = make_float4(v0, v1, v2, v3);
        unsigned int h0, h1;
        PACK2(h0, v0, v1);
        PACK2(h1, v2, v3);
        float e0 = __uint_as_float(h0 << 16);
        float e1 = __uint_as_float(h0 & 0xFFFF0000u);
        float e2 = __uint_as_float(h1 << 16);
        float e3 = __uint_as_float(h1 & 0xFFFF0000u);
        unsigned int l0, l1;
        PACK2(l0, v0 - e0, v1 - e1);
        PACK2(l1, v2 - e2, v3 - e3);
        *(uint2*)&g_fhi[((size_t)r * C + c) / 2] = make_uint2(h0, h1);
        *(uint2*)&g_flo[((size_t)r * C + c) / 2] = make_uint2(l0, l1);
    }
}

// ---------------- phase 2: src/dst + exp factors + maxdst ----------------
__global__ __launch_bounds__(256) void srcdst_kernel(const float* __restrict__ a)
{
    const int warp = threadIdx.x >> 5;
    const int lane = threadIdx.x & 31;
    const int n = blockIdx.x * 8 + warp;
    if (n >= N_NODES) return;

    const float* f = g_feats + (size_t)n * C;

#pragma unroll
    for (int h = 0; h < NH; h++) {
        float f0 = f[h * 64 + lane];
        float f1 = f[h * 64 + 32 + lane];
        float as0 = a[h * 128 + lane];
        float as1 = a[h * 128 + 32 + lane];
        float ad0 = a[h * 128 + 64 + lane];
        float ad1 = a[h * 128 + 96 + lane];
        float vs = f0 * as0 + f1 * as1;
        float vd = f0 * ad0 + f1 * ad1;
#pragma unroll
        for (int o = 16; o; o >>= 1) {
            vs += __shfl_xor_sync(0xFFFFFFFFu, vs, o);
            vd += __shfl_xor_sync(0xFFFFFFFFu, vd, o);
        }
        if (lane == 0) {
            g_src[n * NH + h] = vs;
            g_DE[n * NH + h] = make_float4(vd, expf(vd), expf(ALPHA * vd), 0.f);
            atomicMax(&g_maxdst_enc[h], fenc(vd));
        }
    }
}

// ---------------- phase 3: attention via mma.sync bf16 (split-j) -----------
// grid (NH, N/128, NSPLIT) = 256 blocks, 256 threads (8 warps), 2 blocks/SM.
// Per 32-j chunk: probs -> single-buffered P tiles (hi/lo, row pad 80B);
// F^T tiles [32j][72bf16] double-buffered via cp.async; TWO barriers per
// chunk (P single-buffer) -- overlapped across the 2 resident blocks.
// 48 HMMA/warp/chunk: PhiFhi + PhiFlo + PloFhi. Writes UNNORMALIZED
// partials + exact fp32 denominators; combine kernel normalizes.
static const int OFF_PHI  = 0;        // 10240
static const int OFF_PLO  = 10240;    // 10240
static const int OFF_FHI  = 20480;    // 2 x 4608
static const int OFF_FLO  = 29696;    // 2 x 4608
static const int OFF_DE   = 38912;    // 2 x 32 float4
static const int OFF_RED  = 39936;    // 256 float
static const int ATTN_SMEM = 40960;

__global__ __launch_bounds__(256, 2) void attn_kernel()
{
    extern __shared__ char sb[];
    const unsigned int sbase = sm32(sb);

    const int h    = blockIdx.x;
    const int i0   = blockIdx.y * 128;
    const int sp   = blockIdx.z;
    const int jb   = sp * (N_NODES / NSPLIT);
    const int jw0  = jb / 32;
    const int tid  = threadIdx.x;
    const int wq   = tid >> 5;
    const int lane = tid & 31;
    const int il   = tid & 127;
    const int half = tid >> 7;

    // ---- per-thread softmax factors for row il ----
    float srcv = g_src[(i0 + il) * NH + h];
    float md   = fdec(g_maxdst_enc[h]);
    float bb   = srcv + md;
    bb = (bb >= 0.f) ? bb : ALPHA * bb;        // b_i >= all logits (both splits)
    const float P1 = expf(srcv - bb);
    const float P2 = expf(ALPHA * srcv - bb);
    float den = 0.f;

    // ---- F staging: thread -> (row fj, 16B seg) of the 32x128B chunk ----
    const int fj  = tid >> 3;                  // 0..31
    const int seg = tid & 7;                   // 0..7
    const char* gfh = (const char*)g_fhi + ((size_t)(jb + fj) * C + h * 64) * 2 + seg * 16;
    const char* gfl = (const char*)g_flo + ((size_t)(jb + fj) * C + h * 64) * 2 + seg * 16;
    const unsigned int sFh = sbase + OFF_FHI + fj * 144 + seg * 16;
    const unsigned int sFl = sbase + OFF_FLO + fj * 144 + seg * 16;

    // ---- prologue: F(0) -> slot 0, DE(0), adj word(0) ----
    CP_ASYNC16(sFh, gfh);
    CP_ASYNC16(sFl, gfl);
    CP_COMMIT();
    if (tid < 32)
        *(float4*)(sb + OFF_DE + tid * 16) = g_DE[(size_t)(jb + tid) * NH + h];
    unsigned int word = g_adjbits[(size_t)(i0 + il) * NWORDS + jw0];
    __syncthreads();   // DE(0) visible before probs(0); P free (fresh)

    float d[8][4];
#pragma unroll
    for (int nb = 0; nb < 8; nb++)
#pragma unroll
        for (int q = 0; q < 4; q++) d[nb][q] = 0.f;

    for (int c = 0; c < NCPART; c++) {
        const int buf = c & 1;

        // ---- probs: 16 j for row il, bf16 split, 4x STS.128 ----
        {
            const float4* deb = (const float4*)(sb + OFF_DE + buf * 512);
            float pr[16];
#pragma unroll
            for (int u = 0; u < 16; u++) {
                int jl = half * 16 + u;
                float4 d4 = deb[jl];
                float s = srcv + d4.x;
                float v = (s >= 0.f) ? P1 * d4.y : P2 * d4.z;
                pr[u] = ((word >> jl) & 1u) ? v : 0.f;
                den += pr[u];
            }
            unsigned int hp[8], lp[8];
#pragma unroll
            for (int q = 0; q < 8; q++) {
                unsigned int hh;
                PACK2(hh, pr[2 * q], pr[2 * q + 1]);
                float e0 = __uint_as_float(hh << 16);
                float e1 = __uint_as_float(hh & 0xFFFF0000u);
                unsigned int ll;
                PACK2(ll, pr[2 * q] - e0, pr[2 * q + 1] - e1);
                hp[q] = hh;
                lp[q] = ll;
            }
            char* pH = sb + OFF_PHI + il * 80 + half * 32;
            char* pL = sb + OFF_PLO + il * 80 + half * 32;
            *(uint4*)pH        = make_uint4(hp[0], hp[1], hp[2], hp[3]);
            *(uint4*)(pH + 16) = make_uint4(hp[4], hp[5], hp[6], hp[7]);
            *(uint4*)pL        = make_uint4(lp[0], lp[1], lp[2], lp[3]);
            *(uint4*)(pL + 16) = make_uint4(lp[4], lp[5], lp[6], lp[7]);
        }

        // ---- prefetch chunk c+1 (F slot buf^1 freed by MMA(c-1) barrier) ----
        if (c + 1 < NCPART) {
            const size_t go = (size_t)(c + 1) * JC * C * 2;   // 32 rows x 512B
            CP_ASYNC16(sFh + (buf ^ 1) * 4608, gfh + go);
            CP_ASYNC16(sFl + (buf ^ 1) * 4608, gfl + go);
            CP_COMMIT();
            if (tid < 32)
                *(float4*)(sb + OFF_DE + (buf ^ 1) * 512 + tid * 16) =
                    g_DE[(size_t)(jb + (c + 1) * JC + tid) * NH + h];
            word = g_adjbits[(size_t)(i0 + il) * NWORDS + jw0 + c + 1];
            CP_WAIT1();     // F(c) arrived
        } else {
            CP_WAIT0();
        }
        __syncthreads();    // P(c), F(c), DE(c+1) visible block-wide

        // ---- mma: A = P rows [wq*16,+16) x k32, B = F k32 x n64 ----
        {
            const unsigned int lrow = lane & 15;
            const unsigned int lsel = (lane >> 4) * 16;
            unsigned int pAh = sbase + OFF_PHI + wq * 16 * 80 + lrow * 80 + lsel;
            unsigned int pAl = pAh + (OFF_PLO - OFF_PHI);
            unsigned int pBh = sbase + OFF_FHI + buf * 4608 + lrow * 144 + lsel;
            unsigned int pBl = pBh + (OFF_FLO - OFF_FHI);

            unsigned int aH0[4], aH1[4], aL0[4], aL1[4];
            LDSM4(aH0[0], aH0[1], aH0[2], aH0[3], pAh);
            LDSM4(aH1[0], aH1[1], aH1[2], aH1[3], pAh + 32);
            LDSM4(aL0[0], aL0[1], aL0[2], aL0[3], pAl);
            LDSM4(aL1[0], aL1[1], aL1[2], aL1[3], pAl + 32);

#pragma unroll
            for (int nt = 0; nt < 4; nt++) {
                unsigned int bH0[4], bH1[4], bL0[4], bL1[4];
                LDSM4T(bH0[0], bH0[1], bH0[2], bH0[3], pBh + nt * 32);
                LDSM4T(bH1[0], bH1[1], bH1[2], bH1[3], pBh + 2304 + nt * 32);
                LDSM4T(bL0[0], bL0[1], bL0[2], bL0[3], pBl + nt * 32);
                LDSM4T(bL1[0], bL1[1], bL1[2], bL1[3], pBl + 2304 + nt * 32);
                float* dA = d[nt * 2];
                float* dB = d[nt * 2 + 1];
                MMA(dA, aH0[0], aH0[1], aH0[2], aH0[3], bH0[0], bH0[1]);
                MMA(dB, aH0[0], aH0[1], aH0[2], aH0[3], bH0[2], bH0[3]);
                MMA(dA, aH1[0], aH1[1], aH1[2], aH1[3], bH1[0], bH1[1]);
                MMA(dB, aH1[0], aH1[1], aH1[2], aH1[3], bH1[2], bH1[3]);
                MMA(dA, aH0[0], aH0[1], aH0[2], aH0[3], bL0[0], bL0[1]);
                MMA(dB, aH0[0], aH0[1], aH0[2], aH0[3], bL0[2], bL0[3]);
                MMA(dA, aH1[0], aH1[1], aH1[2], aH1[3], bL1[0], bL1[1]);
                MMA(dB, aH1[0], aH1[1], aH1[2], aH1[3], bL1[2], bL1[3]);
                MMA(dA, aL0[0], aL0[1], aL0[2], aL0[3], bH0[0], bH0[1]);
                MMA(dB, aL0[0], aL0[1], aL0[2], aL0[3], bH0[2], bH0[3]);
                MMA(dA, aL1[0], aL1[1], aL1[2], aL1[3], bH1[0], bH1[1]);
                MMA(dB, aL1[0], aL1[1], aL1[2], aL1[3], bH1[2], bH1[3]);
            }
        }
        __syncthreads();    // all warps done reading P/F(c) before overwrite
    }

    // ---- partial denominators ----
    ((float*)(sb + OFF_RED))[half * 128 + il] = den;
    __syncthreads();
    if (tid < 128) {
        float d0 = ((float*)(sb + OFF_RED))[tid];
        float d1 = ((float*)(sb + OFF_RED))[128 + tid];
        g_pden[sp][(i0 + tid) * NH + h] = d0 + d1;
    }

    // ---- write unnormalized partials ----
    {
        const int g = lane >> 2;
        const int t = lane & 3;
        const int ib = wq * 16;
        float* pacc = g_pacc[sp];
#pragma unroll
        for (int nb = 0; nb < 8; nb++) {
            int col = h * 64 + nb * 8 + 2 * t;
            *(float2*)&pacc[(size_t)(i0 + ib + g) * C + col] =
                make_float2(d[nb][0], d[nb][1]);
            *(float2*)&pacc[(size_t)(i0 + ib + g + 8) * C + col] =
                make_float2(d[nb][2], d[nb][3]);
        }
    }
}

// ---------------- phase 4: combine splits + normalize ----------------
__global__ __launch_bounds__(256) void combine_kernel(float* __restrict__ out)
{
    int idx = blockIdx.x * 256 + threadIdx.x;       // over N*C/4 float4 groups
    int i = idx >> 6;
    int h = (idx >> 4) & 3;
    float4 a = *(const float4*)&g_pacc[0][(size_t)idx * 4];
    float4 b = *(const float4*)&g_pacc[1][(size_t)idx * 4];
    float r = 1.f / (g_pden[0][i * NH + h] + g_pden[1][i * NH + h]);
    float4 v = make_float4((a.x + b.x) * r, (a.y + b.y) * r,
                           (a.z + b.z) * r, (a.w + b.w) * r);
    *(float4*)&out[(size_t)idx * 4] = v;
}

// ---------------- launch ----------------
extern "C" void kernel_launch(void* const* d_in, const int* in_sizes, int n_in,
                              void* d_out, int out_size)
{
    const float* node_feats = (const float*)d_in[0];
    const int*   adj        = (const int*)d_in[1];
    const float* W          = (const float*)d_in[2];
    const float* b          = (const float*)d_in[3];
    const float* a          = (const float*)d_in[4];
    float* out = (float*)d_out;

    cudaFuncSetAttribute(attn_kernel,
                         cudaFuncAttributeMaxDynamicSharedMemorySize, ATTN_SMEM);

    init_kernel<<<1, 32>>>();
    bitpack_kernel<<<N_NODES, 256>>>(adj);
    gemm_feats<<<dim3(C / 64, N_NODES / 64), 256>>>(node_feats, W, b);
    srcdst_kernel<<<N_NODES / 8, 256>>>(a);
    attn_kernel<<<dim3(NH, N_NODES / 128, NSPLIT), 256, ATTN_SMEM>>>();
    combine_kernel<<<(N_NODES * C / 4) / 256, 256>>>(out);
}

// round 17
// speedup vs baseline: 2.0193x; 1.1022x over previous
#include <cuda_runtime.h>
#include <cuda_bf16.h>
#include <math.h>
#include <stdint.h>

#define N_NODES 4096
#define C 256
#define NH 4
#define ALPHA 0.2f
#define NWORDS (N_NODES / 32)   // 128 bitmask words per row
#define JC 32                   // j per chunk
#define NSPLIT 2
#define NCPART (N_NODES / JC / NSPLIT)   // 64 chunks per split

typedef unsigned long long ull;

// ---------------- device scratch (no allocs allowed) ----------------
__device__ float  g_feats[N_NODES * C];              // 4 MB
__device__ float  g_src[N_NODES * NH];
__device__ float4 g_DE[N_NODES * NH];                // (dst, e^dst, e^(a*dst), -)
__device__ unsigned int g_maxdst_enc[NH];
__device__ unsigned int g_adjbits[N_NODES * NWORDS]; // 2 MB bitpacked adjacency
__device__ unsigned int g_fhi[N_NODES * C / 2];      // feats hi bf16x2 [j][hc]
__device__ unsigned int g_flo[N_NODES * C / 2];      // feats lo bf16x2
__device__ float  g_pacc[NSPLIT][N_NODES * C];       // 8 MB unnormalized partials
__device__ float  g_pden[NSPLIT][N_NODES * NH];      // partial denominators

__device__ __forceinline__ unsigned int fenc(float f) {
    unsigned int u = __float_as_uint(f);
    return (u & 0x80000000u) ? ~u : (u | 0x80000000u);
}
__device__ __forceinline__ float fdec(unsigned int u) {
    return (u & 0x80000000u) ? __uint_as_float(u ^ 0x80000000u)
                             : __uint_as_float(~u);
}
__device__ __forceinline__ unsigned int sm32(const void* p) {
    unsigned int a;
    asm("{ .reg .u64 t; cvta.to.shared.u64 t, %1; cvt.u32.u64 %0, t; }"
        : "=r"(a) : "l"(p));
    return a;
}

#define CP_ASYNC16(sa, ga) \
    asm volatile("cp.async.cg.shared.global [%0], [%1], 16;" :: "r"(sa), "l"(ga))
#define CP_COMMIT()  asm volatile("cp.async.commit_group;")
#define CP_WAIT1()   asm volatile("cp.async.wait_group 1;" ::: "memory")
#define CP_WAIT0()   asm volatile("cp.async.wait_group 0;" ::: "memory")

// pack two fp32 -> bf16x2 (low half = lo arg)
#define PACK2(r, lo, hi) \
    asm("cvt.rn.bf16x2.f32 %0, %1, %2;" : "=r"(r) : "f"(hi), "f"(lo))

#define LDSM4(r0, r1, r2, r3, addr) \
    asm volatile("ldmatrix.sync.aligned.m8n8.x4.shared.b16 {%0,%1,%2,%3}, [%4];" \
        : "=r"(r0), "=r"(r1), "=r"(r2), "=r"(r3) : "r"(addr))
#define LDSM4T(r0, r1, r2, r3, addr) \
    asm volatile("ldmatrix.sync.aligned.m8n8.x4.trans.shared.b16 {%0,%1,%2,%3}, [%4];" \
        : "=r"(r0), "=r"(r1), "=r"(r2), "=r"(r3) : "r"(addr))

#define MMA(d, a0, a1, a2, a3, b0, b1) \
    asm volatile("mma.sync.aligned.m16n8k16.row.col.f32.bf16.bf16.f32 " \
        "{%0,%1,%2,%3},{%4,%5,%6,%7},{%8,%9},{%0,%1,%2,%3};" \
        : "+f"((d)[0]), "+f"((d)[1]), "+f"((d)[2]), "+f"((d)[3]) \
        : "r"(a0), "r"(a1), "r"(a2), "r"(a3), "r"(b0), "r"(b1))

// ---------------- init ----------------
__global__ void init_kernel() {
    if (threadIdx.x < NH) g_maxdst_enc[threadIdx.x] = 0u;
}

// ---------------- phase 0: bitpack adjacency ----------------
__global__ __launch_bounds__(256) void bitpack_kernel(const int* __restrict__ adj)
{
    const int i    = blockIdx.x;
    const int wp   = threadIdx.x >> 5;
    const int lane = threadIdx.x & 31;
    const int* row = adj + (size_t)i * N_NODES;
#pragma unroll
    for (int t = 0; t < NWORDS / 8; t++) {
        int jw = wp + t * 8;
        int v  = row[jw * 32 + lane];
        unsigned int m = __ballot_sync(0xFFFFFFFFu, v == 1);
        if (lane == 0) g_adjbits[i * NWORDS + jw] = m;
    }
}

// ---------------- phase 1: feats = X @ W + b  (+ fused bf16 hi/lo split) ----
__global__ __launch_bounds__(256) void gemm_feats(
    const float* __restrict__ X, const float* __restrict__ W,
    const float* __restrict__ bias)
{
    __shared__ float As[16][64];
    __shared__ float Bs[16][64];

    const int tid = threadIdx.x;
    const int tx = tid & 15;
    const int ty = tid >> 4;
    const int bm = blockIdx.y * 64;
    const int bn = blockIdx.x * 64;

    float acc[4][4] = {};

    for (int k0 = 0; k0 < C; k0 += 16) {
        {
            int row = tid >> 2;
            int kc  = (tid & 3) * 4;
            float4 v = *(const float4*)&X[(size_t)(bm + row) * C + k0 + kc];
            As[kc + 0][row] = v.x;
            As[kc + 1][row] = v.y;
            As[kc + 2][row] = v.z;
            As[kc + 3][row] = v.w;
        }
        {
            int kr = tid >> 4;
            int cc = (tid & 15) * 4;
            *(float4*)&Bs[kr][cc] =
                *(const float4*)&W[(size_t)(k0 + kr) * C + bn + cc];
        }
        __syncthreads();

#pragma unroll
        for (int kk = 0; kk < 16; kk++) {
            float4 a4 = *(const float4*)&As[kk][ty * 4];
            float4 b4 = *(const float4*)&Bs[kk][tx * 4];
            float av[4] = {a4.x, a4.y, a4.z, a4.w};
            float bv[4] = {b4.x, b4.y, b4.z, b4.w};
#pragma unroll
            for (int i = 0; i < 4; i++)
#pragma unroll
                for (int j = 0; j < 4; j++)
                    acc[i][j] += av[i] * bv[j];
        }
        __syncthreads();
    }

    // epilogue: write fp32 feats + bf16 hi/lo splits (fused feat_split)
#pragma unroll
    for (int i = 0; i < 4; i++) {
        int r = bm + ty * 4 + i;
        int c = bn + tx * 4;
        float v0 = acc[i][0] + bias[c];
        float v1 = acc[i][1] + bias[c + 1];
        float v2 = acc[i][2] + bias[c + 2];
        float v3 = acc[i][3] + bias[c + 3];
        *(float4*)&g_feats[(size_t)r * C + c] = make_float4(v0, v1, v2, v3);
        unsigned int h0, h1;
        PACK2(h0, v0, v1);
        PACK2(h1, v2, v3);
        float e0 = __uint_as_float(h0 << 16);
        float e1 = __uint_as_float(h0 & 0xFFFF0000u);
        float e2 = __uint_as_float(h1 << 16);
        float e3 = __uint_as_float(h1 & 0xFFFF0000u);
        unsigned int l0, l1;
        PACK2(l0, v0 - e0, v1 - e1);
        PACK2(l1, v2 - e2, v3 - e3);
        *(uint2*)&g_fhi[((size_t)r * C + c) / 2] = make_uint2(h0, h1);
        *(uint2*)&g_flo[((size_t)r * C + c) / 2] = make_uint2(l0, l1);
    }
}

// ---------------- phase 2: src/dst + exp factors + maxdst (vectorized) ------
// one warp per node; lane owns 8 channels (2 LDG.128), head hg = lane>>3;
// 3-level shfl reduce within each 8-lane head group.
__global__ __launch_bounds__(256) void srcdst_kernel(const float* __restrict__ a)
{
    const int warp = threadIdx.x >> 5;
    const int lane = threadIdx.x & 31;
    const int n = blockIdx.x * 8 + warp;

    const int hg = lane >> 3;          // head of this lane group
    const int lo = (lane & 7) * 8;     // channel offset within head

    const float* f = g_feats + (size_t)n * C + hg * 64 + lo;
    const float* as = a + hg * 128 + lo;
    const float* ad = as + 64;

    float4 v0 = *(const float4*)f;
    float4 v1 = *(const float4*)(f + 4);
    float4 s0 = *(const float4*)as;
    float4 s1 = *(const float4*)(as + 4);
    float4 d0 = *(const float4*)ad;
    float4 d1 = *(const float4*)(ad + 4);

    float vs = v0.x * s0.x + v0.y * s0.y + v0.z * s0.z + v0.w * s0.w
             + v1.x * s1.x + v1.y * s1.y + v1.z * s1.z + v1.w * s1.w;
    float vd = v0.x * d0.x + v0.y * d0.y + v0.z * d0.z + v0.w * d0.w
             + v1.x * d1.x + v1.y * d1.y + v1.z * d1.z + v1.w * d1.w;

#pragma unroll
    for (int o = 4; o; o >>= 1) {
        vs += __shfl_xor_sync(0xFFFFFFFFu, vs, o);
        vd += __shfl_xor_sync(0xFFFFFFFFu, vd, o);
    }
    if ((lane & 7) == 0) {
        g_src[n * NH + hg] = vs;
        g_DE[n * NH + hg] = make_float4(vd, expf(vd), expf(ALPHA * vd), 0.f);
        atomicMax(&g_maxdst_enc[hg], fenc(vd));
    }
}

// ---------------- phase 3: attention via mma.sync bf16 (split-j) -----------
// grid (NH, N/128, NSPLIT) = 256 blocks, 256 threads (8 warps), 2 blocks/SM.
// P tiles DOUBLE-buffered, F^T tiles TRIPLE-buffered -> ONE barrier per
// chunk: probs(c) -> prefetch(c+1) -> barrier -> MMA(c). Hazard audit:
// P[c&1] last read by MMA(c-2) (all warps pre-barrier(c-1)); F[(c+1)%3]
// last read by MMA(c-2); DE ping-pong covered by the same barrier.
// 48 HMMA/warp/chunk: PhiFhi + PhiFlo + PloFhi. Writes UNNORMALIZED
// partials + exact fp32 denominators; combine kernel normalizes.
static const int OFF_PHI  = 0;        // 2 x 10240
static const int OFF_PLO  = 20480;    // 2 x 10240
static const int OFF_FHI  = 40960;    // 3 x 4608
static const int OFF_FLO  = 54784;    // 3 x 4608
static const int OFF_DE   = 68608;    // 2 x 32 float4
static const int OFF_RED  = 69632;    // 256 float
static const int ATTN_SMEM = 70656;

__global__ __launch_bounds__(256, 2) void attn_kernel()
{
    extern __shared__ char sb[];
    const unsigned int sbase = sm32(sb);

    const int h    = blockIdx.x;
    const int i0   = blockIdx.y * 128;
    const int sp   = blockIdx.z;
    const int jb   = sp * (N_NODES / NSPLIT);
    const int jw0  = jb / 32;
    const int tid  = threadIdx.x;
    const int wq   = tid >> 5;
    const int lane = tid & 31;
    const int il   = tid & 127;
    const int half = tid >> 7;

    // ---- per-thread softmax factors for row il ----
    float srcv = g_src[(i0 + il) * NH + h];
    float md   = fdec(g_maxdst_enc[h]);
    float bb   = srcv + md;
    bb = (bb >= 0.f) ? bb : ALPHA * bb;        // b_i >= all logits (both splits)
    const float P1 = expf(srcv - bb);
    const float P2 = expf(ALPHA * srcv - bb);
    float den = 0.f;

    // ---- F staging: thread -> (row fj, 16B seg) of the 32x128B chunk ----
    const int fj  = tid >> 3;                  // 0..31
    const int seg = tid & 7;                   // 0..7
    const char* gfh = (const char*)g_fhi + ((size_t)(jb + fj) * C + h * 64) * 2 + seg * 16;
    const char* gfl = (const char*)g_flo + ((size_t)(jb + fj) * C + h * 64) * 2 + seg * 16;
    const unsigned int sFh = sbase + OFF_FHI + fj * 144 + seg * 16;
    const unsigned int sFl = sbase + OFF_FLO + fj * 144 + seg * 16;

    // ---- prologue: F(0) -> slot 0, DE(0), adj word(0) ----
    CP_ASYNC16(sFh, gfh);
    CP_ASYNC16(sFl, gfl);
    CP_COMMIT();
    if (tid < 32)
        *(float4*)(sb + OFF_DE + tid * 16) = g_DE[(size_t)(jb + tid) * NH + h];
    unsigned int word = g_adjbits[(size_t)(i0 + il) * NWORDS + jw0];
    __syncthreads();   // DE(0) visible before probs(0)

    float d[8][4];
#pragma unroll
    for (int nb = 0; nb < 8; nb++)
#pragma unroll
        for (int q = 0; q < 4; q++) d[nb][q] = 0.f;

    for (int c = 0; c < NCPART; c++) {
        const int buf   = c & 1;
        const int fslot = c % 3;

        // ---- probs: 16 j for row il, bf16 split, 4x STS.128 -> P[buf] ----
        {
            const float4* deb = (const float4*)(sb + OFF_DE + buf * 512);
            float pr[16];
#pragma unroll
            for (int u = 0; u < 16; u++) {
                int jl = half * 16 + u;
                float4 d4 = deb[jl];
                float s = srcv + d4.x;
                float v = (s >= 0.f) ? P1 * d4.y : P2 * d4.z;
                pr[u] = ((word >> jl) & 1u) ? v : 0.f;
                den += pr[u];
            }
            unsigned int hp[8], lp[8];
#pragma unroll
            for (int q = 0; q < 8; q++) {
                unsigned int hh;
                PACK2(hh, pr[2 * q], pr[2 * q + 1]);
                float e0 = __uint_as_float(hh << 16);
                float e1 = __uint_as_float(hh & 0xFFFF0000u);
                unsigned int ll;
                PACK2(ll, pr[2 * q] - e0, pr[2 * q + 1] - e1);
                hp[q] = hh;
                lp[q] = ll;
            }
            char* pH = sb + OFF_PHI + buf * 10240 + il * 80 + half * 32;
            char* pL = sb + OFF_PLO + buf * 10240 + il * 80 + half * 32;
            *(uint4*)pH        = make_uint4(hp[0], hp[1], hp[2], hp[3]);
            *(uint4*)(pH + 16) = make_uint4(hp[4], hp[5], hp[6], hp[7]);
            *(uint4*)pL        = make_uint4(lp[0], lp[1], lp[2], lp[3]);
            *(uint4*)(pL + 16) = make_uint4(lp[4], lp[5], lp[6], lp[7]);
        }

        // ---- prefetch chunk c+1: F -> slot (c+1)%3, DE -> slot (c+1)&1 ----
        if (c + 1 < NCPART) {
            const int ns = (c + 1) % 3;
            const size_t go = (size_t)(c + 1) * JC * C * 2;   // 32 rows x 512B
            CP_ASYNC16(sFh + ns * 4608, gfh + go);
            CP_ASYNC16(sFl + ns * 4608, gfl + go);
            CP_COMMIT();
            if (tid < 32)
                *(float4*)(sb + OFF_DE + (buf ^ 1) * 512 + tid * 16) =
                    g_DE[(size_t)(jb + (c + 1) * JC + tid) * NH + h];
            word = g_adjbits[(size_t)(i0 + il) * NWORDS + jw0 + c + 1];
            CP_WAIT1();     // F(c) arrived (F(c+1) still in flight)
        } else {
            CP_WAIT0();
        }
        __syncthreads();    // P(c), F(c), DE(c+1) visible block-wide

        // ---- mma: A = P rows [wq*16,+16) x k32, B = F k32 x n64 ----
        {
            const unsigned int lrow = lane & 15;
            const unsigned int lsel = (lane >> 4) * 16;
            unsigned int pAh = sbase + OFF_PHI + buf * 10240 + wq * 16 * 80
                               + lrow * 80 + lsel;
            unsigned int pAl = pAh + (OFF_PLO - OFF_PHI);
            unsigned int pBh = sbase + OFF_FHI + fslot * 4608 + lrow * 144 + lsel;
            unsigned int pBl = pBh + (OFF_FLO - OFF_FHI);

            unsigned int aH0[4], aH1[4], aL0[4], aL1[4];
            LDSM4(aH0[0], aH0[1], aH0[2], aH0[3], pAh);
            LDSM4(aH1[0], aH1[1], aH1[2], aH1[3], pAh + 32);
            LDSM4(aL0[0], aL0[1], aL0[2], aL0[3], pAl);
            LDSM4(aL1[0], aL1[1], aL1[2], aL1[3], pAl + 32);

#pragma unroll
            for (int nt = 0; nt < 4; nt++) {
                unsigned int bH0[4], bH1[4], bL0[4], bL1[4];
                LDSM4T(bH0[0], bH0[1], bH0[2], bH0[3], pBh + nt * 32);
                LDSM4T(bH1[0], bH1[1], bH1[2], bH1[3], pBh + 2304 + nt * 32);
                LDSM4T(bL0[0], bL0[1], bL0[2], bL0[3], pBl + nt * 32);
                LDSM4T(bL1[0], bL1[1], bL1[2], bL1[3], pBl + 2304 + nt * 32);
                float* dA = d[nt * 2];
                float* dB = d[nt * 2 + 1];
                MMA(dA, aH0[0], aH0[1], aH0[2], aH0[3], bH0[0], bH0[1]);
                MMA(dB, aH0[0], aH0[1], aH0[2], aH0[3], bH0[2], bH0[3]);
                MMA(dA, aH1[0], aH1[1], aH1[2], aH1[3], bH1[0], bH1[1]);
                MMA(dB, aH1[0], aH1[1], aH1[2], aH1[3], bH1[2], bH1[3]);
                MMA(dA, aH0[0], aH0[1], aH0[2], aH0[3], bL0[0], bL0[1]);
                MMA(dB, aH0[0], aH0[1], aH0[2], aH0[3], bL0[2], bL0[3]);
                MMA(dA, aH1[0], aH1[1], aH1[2], aH1[3], bL1[0], bL1[1]);
                MMA(dB, aH1[0], aH1[1], aH1[2], aH1[3], bL1[2], bL1[3]);
                MMA(dA, aL0[0], aL0[1], aL0[2], aL0[3], bH0[0], bH0[1]);
                MMA(dB, aL0[0], aL0[1], aL0[2], aL0[3], bH0[2], bH0[3]);
                MMA(dA, aL1[0], aL1[1], aL1[2], aL1[3], bH1[0], bH1[1]);
                MMA(dB, aL1[0], aL1[1], aL1[2], aL1[3], bH1[2], bH1[3]);
            }
        }
    }

    // ---- partial denominators ----
    ((float*)(sb + OFF_RED))[half * 128 + il] = den;
    __syncthreads();
    if (tid < 128) {
        float d0 = ((float*)(sb + OFF_RED))[tid];
        float d1 = ((float*)(sb + OFF_RED))[128 + tid];
        g_pden[sp][(i0 + tid) * NH + h] = d0 + d1;
    }

    // ---- write unnormalized partials ----
    {
        const int g = lane >> 2;
        const int t = lane & 3;
        const int ib = wq * 16;
        float* pacc = g_pacc[sp];
#pragma unroll
        for (int nb = 0; nb < 8; nb++) {
            int col = h * 64 + nb * 8 + 2 * t;
            *(float2*)&pacc[(size_t)(i0 + ib + g) * C + col] =
                make_float2(d[nb][0], d[nb][1]);
            *(float2*)&pacc[(size_t)(i0 + ib + g + 8) * C + col] =
                make_float2(d[nb][2], d[nb][3]);
        }
    }
}

// ---------------- phase 4: combine splits + normalize ----------------
__global__ __launch_bounds__(256) void combine_kernel(float* __restrict__ out)
{
    int idx = blockIdx.x * 256 + threadIdx.x;       // over N*C/4 float4 groups
    int i = idx >> 6;
    int h = (idx >> 4) & 3;
    float4 a = *(const float4*)&g_pacc[0][(size_t)idx * 4];
    float4 b = *(const float4*)&g_pacc[1][(size_t)idx * 4];
    float r = 1.f / (g_pden[0][i * NH + h] + g_pden[1][i * NH + h]);
    float4 v = make_float4((a.x + b.x) * r, (a.y + b.y) * r,
                           (a.z + b.z) * r, (a.w + b.w) * r);
    *(float4*)&out[(size_t)idx * 4] = v;
}

// ---------------- launch ----------------
extern "C" void kernel_launch(void* const* d_in, const int* in_sizes, int n_in,
                              void* d_out, int out_size)
{
    const float* node_feats = (const float*)d_in[0];
    const int*   adj        = (const int*)d_in[1];
    const float* W          = (const float*)d_in[2];
    const float* b          = (const float*)d_in[3];
    const float* a          = (const float*)d_in[4];
    float* out = (float*)d_out;

    cudaFuncSetAttribute(attn_kernel,
                         cudaFuncAttributeMaxDynamicSharedMemorySize, ATTN_SMEM);

    init_kernel<<<1, 32>>>();
    bitpack_kernel<<<N_NODES, 256>>>(adj);
    gemm_feats<<<dim3(C / 64, N_NODES / 64), 256>>>(node_feats, W, b);
    srcdst_kernel<<<N_NODES / 8, 256>>>(a);
    attn_kernel<<<dim3(NH, N_NODES / 128, NSPLIT), 256, ATTN_SMEM>>>();
    combine_kernel<<<(N_NODES * C / 4) / 256, 256>>>(out);
}